// round 11
// baseline (speedup 1.0000x reference)
#include <cuda_runtime.h>
#include <cstdint>

// Problem constants
#define B    16
#define H    512
#define W    512
#define KR   15                   // pad / half-window
#define INV_WIN2 (1.0f / 961.0f)

#define NT    256
#define RSEG1 16                  // rows per K1 block
#define GRID1 (B * H / RSEG1)     // 512
#define RSEG2 8                   // rows per K2 block
#define GRID2 (B * H / RSEG2)     // 1024
#define WPR   16                  // bit words per row

__device__ uint32_t g_bits[B * H * WPR];      // 512 KB mask bit-plane
__device__ uint8_t  g_hsum[B * H * W];        // 4 MB horizontal 31-popcounts
__device__ float4   g_part[GRID2];            // per-block partial sums
__device__ int      g_done;                   // zero-init; self-resets

// ---------------------------------------------------------------------------
// Build one 32-column bitmask word in one thread. bit = (v==1); {0,255}->0.
// ---------------------------------------------------------------------------
template <bool IS64>
__device__ __forceinline__ uint32_t pack_word(const int* __restrict__ m,
                                              size_t gw)
{
    uint32_t word = 0;
    if (IS64) {
        const int4* p = (const int4*)m + gw * 16;
#pragma unroll
        for (int j = 0; j < 16; ++j) {            // 16 independent LDG.128
            int4 q = p[j];                        // two int64: lows at .x/.z
            word |= (((uint32_t)(q.x == 1)) |
                     ((uint32_t)(q.z == 1) << 1)) << (2 * j);
        }
    } else {
        const int4* p = (const int4*)m + gw * 8;
#pragma unroll
        for (int j = 0; j < 8; ++j) {             // 8 independent LDG.128
            int4 q = p[j];
            word |= (((uint32_t)(q.x == 1))      |
                     ((uint32_t)(q.y == 1) << 1) |
                     ((uint32_t)(q.z == 1) << 2) |
                     ((uint32_t)(q.w == 1) << 3)) << (4 * j);
        }
    }
    return word;
}

// 2-column horizontal 31-bit window popcounts sharing 3 padded-word loads.
// rw = padded row [pad, w0..w15, pad]; dw = (2t)>>5.
__device__ __forceinline__ void hcount2(const uint32_t* __restrict__ rw,
                                        int dw, const int* __restrict__ sel,
                                        const int* __restrict__ sh,
                                        int* __restrict__ out)
{
    const uint32_t p0 = rw[dw], p1 = rw[dw + 1], p2 = rw[dw + 2];
#pragma unroll
    for (int i = 0; i < 2; ++i) {
        uint32_t lo = sel[i] ? p1 : p0;
        uint32_t hi = sel[i] ? p2 : p1;
        out[i] = __popc(__funnelshift_r(lo, hi, sh[i]) & 0x7FFFFFFFu);
    }
}

// ---------------------------------------------------------------------------
// K1: pack mask into bits + write horizontal popcount plane.
// Block = 16 rows of one image; 256 threads. In-kernel dtype probe:
// int64 LE high words all zero; int32 {0,1} data nonzero w.p. 1-2^-256.
// ---------------------------------------------------------------------------
__global__ void __launch_bounds__(NT)
prep_kernel(const int* __restrict__ mask)
{
    const int bi   = blockIdx.x >> 5;
    const int rs   = blockIdx.x & 31;
    const int yb   = rs * RSEG1;
    const int t    = threadIdx.x;

    __shared__ uint32_t words[RSEG1][WPR + 2];    // padded rows

    const unsigned hiw = ((const unsigned*)mask)[2 * t + 1];
    const int is32 = __syncthreads_or(hiw != 0u);

    // Zero pads.
    if (t < 2 * RSEG1) words[t >> 1][(t & 1) ? (WPR + 1) : 0] = 0u;

    // Phase 1: one word per thread (16 rows x 16 words = 256 tasks).
    {
        const int r  = t >> 4;
        const int wi = t & 15;
        const size_t gw = (size_t)bi * (H * WPR) + (size_t)(yb + r) * WPR + wi;
        uint32_t word = is32 ? pack_word<false>(mask, gw)
                             : pack_word<true >(mask, gw);
        words[r][1 + wi] = word;
        g_bits[gw] = word;
    }
    __syncthreads();

    // Phase 2: horizontal popcounts, 2 cols x 16 rows per thread.
    const int dw = t >> 4;
    const int lq = (2 * t) & 31;
    int sel[2], sh[2];
#pragma unroll
    for (int i = 0; i < 2; ++i) {
        sel[i] = (lq + i) >= 15;
        sh[i]  = (lq + i + 17) & 31;
    }
    uint8_t* hb = g_hsum + (size_t)bi * (H * W) + (size_t)yb * W + 2 * t;
#pragma unroll
    for (int r = 0; r < RSEG1; ++r) {
        int hc[2];
        hcount2(words[r], dw, sel, sh, hc);
        *(uchar2*)(hb + (size_t)r * W) =
            make_uchar2((uint8_t)hc[0], (uint8_t)hc[1]);
    }
}

// Per-pixel fused math.
__device__ __forceinline__ void pixel(float a0, float a1, int mi, float pooled,
                                      float& aw, float& awb, float& ai, float& ac)
{
    const float mf = (float)mi;
    const float wgt = 1.0f + 5.0f * fabsf(pooled - mf);

    // 2-class log-softmax, softplus form: d = a1-a0, e = exp(-|d|)
    const float d  = a1 - a0;
    const float e  = __expf(-fabsf(d));
    const float sp = __logf(1.0f + e);
    const float wb = sp + fmaxf(mi ? -d : d, 0.0f);   // -logp[target]
    const float rc = __frcp_rn(1.0f + e);
    const float sp1 = (d >= 0.0f) ? rc : e * rc;      // sigmoid(d) = p1

    aw  += wgt;
    awb += wgt * wb;
    ai  += sp1 * mf * wgt;
    ac  += (sp1 + mf) * wgt;
}

// ---------------------------------------------------------------------------
// K2: barrier-free main kernel. Block = 8 rows of one image; thread t owns
// columns 2t, 2t+1. Pooled from vertical sliding sum of g_hsum (exact ints);
// mask bit from g_bits; pred direct. No smem/syncs until reduction.
// ---------------------------------------------------------------------------
__global__ void __launch_bounds__(NT)
main_kernel(const float* __restrict__ pred, float* __restrict__ out)
{
    const int bi  = blockIdx.x >> 6;
    const int seg = blockIdx.x & 63;
    const int y0  = seg * RSEG2;
    const int t   = threadIdx.x;
    const int lane = t & 31;
    const int w    = t >> 5;

    const int dw = t >> 4;                  // bits word index of cols 2t,2t+1
    const int lq = (2 * t) & 31;

    const uint8_t*  hb = g_hsum + (size_t)bi * (H * W) + 2 * t;
    const uint32_t* bb = g_bits + (size_t)bi * (H * WPR) + dw;
    const float* p0 = pred + (size_t)bi * 524288 + 2 * t;   // ch0
    const float* p1 = p0 + 262144;                          // ch1

    // vsum init for row y0: window rows y0-15..y0+15 (independent loads).
    int vs0 = 0, vs1 = 0;
#pragma unroll
    for (int k = -KR; k <= KR; ++k) {
        const int y = y0 + k;
        if (y >= 0 && y < H) {
            uchar2 hv = *(const uchar2*)(hb + (size_t)y * W);
            vs0 += hv.x; vs1 += hv.y;
        }
    }

    float aw = 0.0f, awb = 0.0f, ai = 0.0f, ac = 0.0f;

#pragma unroll
    for (int r = 0; r < RSEG2; ++r) {
        const int y = y0 + r;

        const uint32_t cw = bb[(size_t)y * WPR];
        const float2 a0 = *(const float2*)(p0 + (size_t)y * W);
        const float2 a1 = *(const float2*)(p1 + (size_t)y * W);

        pixel(a0.x, a1.x, (cw >> lq) & 1,
              (float)vs0 * INV_WIN2, aw, awb, ai, ac);
        pixel(a0.y, a1.y, (cw >> (lq + 1)) & 1,
              (float)vs1 * INV_WIN2, aw, awb, ai, ac);

        // slide vertical windows: +row(y+16), -row(y-15); exact integers.
        const int ya = y + KR + 1;
        const int yr = y - KR;
        if (ya < H) {
            uchar2 hv = *(const uchar2*)(hb + (size_t)ya * W);
            vs0 += hv.x; vs1 += hv.y;
        }
        if (yr >= 0) {
            uchar2 hv = *(const uchar2*)(hb + (size_t)yr * W);
            vs0 -= hv.x; vs1 -= hv.y;
        }
    }

    // Deterministic reduction: warp butterfly + fixed-order combine.
#pragma unroll
    for (int o = 16; o > 0; o >>= 1) {
        aw  += __shfl_xor_sync(0xFFFFFFFFu, aw,  o);
        awb += __shfl_xor_sync(0xFFFFFFFFu, awb, o);
        ai  += __shfl_xor_sync(0xFFFFFFFFu, ai,  o);
        ac  += __shfl_xor_sync(0xFFFFFFFFu, ac,  o);
    }
    __shared__ float4 s4[NT / 32];
    __shared__ int amLast;
    if (lane == 0) s4[w] = make_float4(aw, awb, ai, ac);
    __syncthreads();
    if (t == 0) {
        float4 acc = s4[0];
#pragma unroll
        for (int i = 1; i < NT / 32; ++i) {
            float4 p = s4[i];
            acc.x += p.x; acc.y += p.y; acc.z += p.z; acc.w += p.w;
        }
        g_part[blockIdx.x] = acc;
        __threadfence();
        amLast = (atomicAdd(&g_done, 1) == GRID2 - 1);
    }
    __syncthreads();

    // Last block finalizes (deterministic fixed-order reads of g_part).
    if (amLast) {
        __shared__ double sh2[B];
        if (t < B) {
            double taw = 0.0, tawb = 0.0, tai = 0.0, tac = 0.0;
            for (int s = 0; s < 64; ++s) {
                float4 p = g_part[t * 64 + s];
                taw += p.x; tawb += p.y; tai += p.z; tac += p.w;
            }
            double wbce = tawb / taw;
            double uni  = tac - tai;
            double wiou = 1.0 - (tai + 1.0) / (uni + 1.0);
            sh2[t] = wbce + wiou;
        }
        __syncthreads();
        if (t == 0) {
            double z = 0.0;
#pragma unroll
            for (int i = 0; i < B; ++i) z += sh2[i];
            out[0] = (float)(z / (double)B);
            g_done = 0;   // reset for next (graph-replayed) execution
        }
    }
}

// ---------------------------------------------------------------------------
extern "C" void kernel_launch(void* const* d_in, const int* in_sizes, int n_in,
                              void* d_out, int out_size)
{
    // Identify inputs by element count (robust to metadata ordering):
    // pred = 16*2*512*512 = 8388608, mask = 16*512*512 = 4194304.
    int pi = 0, mi = 1;
    if (n_in >= 2 && in_sizes[0] == 4194304 && in_sizes[1] == 8388608) {
        pi = 1; mi = 0;
    }
    const float* pred = (const float*)d_in[pi];  // [16,2,512,512] fp32
    const int*   mask = (const int*)d_in[mi];    // [16,512,512] int32 OR int64
    float* out = (float*)d_out;

    prep_kernel<<<GRID1, NT>>>(mask);
    main_kernel<<<GRID2, NT>>>(pred, out);
}

// round 14
// speedup vs baseline: 1.3462x; 1.3462x over previous
#include <cuda_runtime.h>
#include <cstdint>

// Problem constants
#define B    16
#define H    512
#define W    512
#define KR   15                   // pad / half-window
#define INV_WIN2 (1.0f / 961.0f)

#define SEGS 16                   // row segments per image
#define ROWS 32                   // rows per block
#define HALO 63                   // rows y0-15 .. y0+47
#define RD   64                   // ring depth (63 distinct rows -> no reuse)
#define RW   18                   // 16 data words + 2 zero pads
#define WPR  16                   // bit words per row
#define NT   512                  // threads per block (1 column each)
#define GRID (B * SEGS)           // 256

__device__ float4 g_part[GRID];   // per-block partial sums
__device__ int    g_done;         // zero-init; self-resets each run

// ---------------------------------------------------------------------------
// Build one 32-column bitmask word in one thread. bit = (v==1); {0,255}->0.
// gw = global word index (bi*8192 + row*16 + wi).
// ---------------------------------------------------------------------------
template <bool IS64>
__device__ __forceinline__ uint32_t pack_word(const int* __restrict__ m,
                                              size_t gw)
{
    uint32_t word = 0;
    if (IS64) {
        const int4* p = (const int4*)m + gw * 16;
#pragma unroll
        for (int j = 0; j < 16; ++j) {            // 16 independent LDG.128
            int4 q = p[j];                        // two int64: lows at .x/.z
            word |= (((uint32_t)(q.x == 1)) |
                     ((uint32_t)(q.z == 1) << 1)) << (2 * j);
        }
    } else {
        const int4* p = (const int4*)m + gw * 8;
#pragma unroll
        for (int j = 0; j < 8; ++j) {             // 8 independent LDG.128
            int4 q = p[j];
            word |= (((uint32_t)(q.x == 1))      |
                     ((uint32_t)(q.y == 1) << 1) |
                     ((uint32_t)(q.z == 1) << 2) |
                     ((uint32_t)(q.w == 1) << 3)) << (4 * j);
        }
    }
    return word;
}

// Horizontal 31-bit window popcount for column = lane of word w, from a
// padded ring row [pad, w0..w15, pad]. (Formula verified in R4, rel_err 0.)
__device__ __forceinline__ int hcount(const uint32_t* __restrict__ rw,
                                      int base, int sh)
{
    uint32_t lo = rw[base], hi = rw[base + 1];
    return __popc(__funnelshift_r(lo, hi, sh) & 0x7FFFFFFFu);
}

// Per-pixel fused math.
__device__ __forceinline__ void pixel(float a0, float a1, int mi, float pooled,
                                      float& aw, float& awb, float& ai, float& ac)
{
    const float mf = (float)mi;
    const float wgt = 1.0f + 5.0f * fabsf(pooled - mf);

    // 2-class log-softmax, softplus form: d = a1-a0, e = exp(-|d|)
    const float d  = a1 - a0;
    const float e  = __expf(-fabsf(d));
    const float sp = __logf(1.0f + e);
    const float wb = sp + fmaxf(mi ? -d : d, 0.0f);   // -logp[target]
    const float rc = __frcp_rn(1.0f + e);
    const float sp1 = (d >= 0.0f) ? rc : e * rc;      // sigmoid(d) = p1

    aw  += wgt;
    awb += wgt * wb;
    ai  += sp1 * mf * wgt;
    ac  += (sp1 + mf) * wgt;
}

// ---------------------------------------------------------------------------
// Single fused kernel. One block per (image, 32-row segment); thread t owns
// column t for all 32 rows. Phase 1 packs 63 halo rows of mask bits into a
// smem ring; phase 2 caches per-row horizontal 31-popcounts in smem (uint8);
// phase 3 is barrier-free compute with a sliding vertical sum.
// ---------------------------------------------------------------------------
template <bool IS64>
__device__ __forceinline__ void fused_body(const float* __restrict__ pred,
                                           const int* __restrict__ mask,
                                           float* __restrict__ out)
{
    const int bi   = blockIdx.x >> 4;          // /SEGS
    const int seg  = blockIdx.x & (SEGS - 1);
    const int y0   = seg * ROWS;
    const int t    = threadIdx.x;
    const int lane = t & 31;
    const int w    = t >> 5;

    const int base = w + (lane >= 15);         // hcount word select
    const int sh   = (lane + 17) & 31;         // hcount funnel shift

    __shared__ uint32_t ring[RD][RW];          // 4.6 KB padded bitmask rows
    __shared__ uint8_t  hsumS[RD][W];          // 32 KB per-row 31-popcounts

    // Zero pad words (row-invariant zeros); covered by first sync.
    if (t < 2 * RD) ring[t >> 1][(t & 1) ? (RW - 1) : 0] = 0u;

    // Phase 1: pack 63 halo rows (y0-15 .. y0+47), 16 words each = 1008
    // tasks; ~2 per thread, each a batch of independent LDG.128.
    for (int task = t; task < HALO * WPR; task += NT) {
        const int row = y0 - 15 + (task >> 4);
        const int wi  = task & 15;
        uint32_t word = 0u;
        if (row >= 0 && row < H)
            word = pack_word<IS64>(mask,
                    (size_t)bi * (H * WPR) + (size_t)row * WPR + wi);
        ring[row & (RD - 1)][1 + wi] = word;
    }
    __syncthreads();

    // Phase 2: horizontal popcount for this column, all 63 rows (independent).
#pragma unroll 1
    for (int k = 0; k < HALO; ++k) {
        const int slot = (y0 - 15 + k) & (RD - 1);
        hsumS[slot][t] = (uint8_t)hcount(ring[slot], base, sh);
    }
    __syncthreads();

    // vsum init for row y0 (window rows y0-15..y0+15; OOB rows hold zeros).
    int vs = 0;
#pragma unroll
    for (int k = -KR; k <= KR; ++k)
        vs += hsumS[(y0 + k) & (RD - 1)][t];

    // Phase 3: barrier-free compute of 32 rows. Full unroll lets ptxas
    // front-batch the independent pred LDGs across rows.
    const float* p0 = pred + (size_t)bi * 524288 + t;   // ch0, column t
    const float* p1 = p0 + 262144;                      // ch1
    float aw = 0.0f, awb = 0.0f, ai = 0.0f, ac = 0.0f;

#pragma unroll
    for (int r = 0; r < ROWS; ++r) {
        const int y = y0 + r;

        const int mi = (ring[y & (RD - 1)][1 + w] >> lane) & 1;
        const float a0 = p0[(size_t)y * W];
        const float a1 = p1[(size_t)y * W];

        pixel(a0, a1, mi, (float)vs * INV_WIN2, aw, awb, ai, ac);

        // slide vertical window: +row(y+16), -row(y-15); exact integers
        // (OOB rows hold zeros in hsumS).
        vs += (int)hsumS[(y + KR + 1) & (RD - 1)][t]
            - (int)hsumS[(y - KR) & (RD - 1)][t];
    }

    // Deterministic reduction: warp butterfly + fixed-order combine.
#pragma unroll
    for (int o = 16; o > 0; o >>= 1) {
        aw  += __shfl_xor_sync(0xFFFFFFFFu, aw,  o);
        awb += __shfl_xor_sync(0xFFFFFFFFu, awb, o);
        ai  += __shfl_xor_sync(0xFFFFFFFFu, ai,  o);
        ac  += __shfl_xor_sync(0xFFFFFFFFu, ac,  o);
    }
    __shared__ float4 s4[NT / 32];
    __shared__ int amLast;
    if (lane == 0) s4[w] = make_float4(aw, awb, ai, ac);
    __syncthreads();
    if (t == 0) {
        float4 acc = s4[0];
#pragma unroll
        for (int i = 1; i < NT / 32; ++i) {
            float4 p = s4[i];
            acc.x += p.x; acc.y += p.y; acc.z += p.z; acc.w += p.w;
        }
        g_part[blockIdx.x] = acc;
        __threadfence();
        amLast = (atomicAdd(&g_done, 1) == GRID - 1);
    }
    __syncthreads();

    // Last block finalizes (deterministic fixed-order reads of g_part).
    if (amLast) {
        __shared__ double sh2[B];
        if (t < B) {
            double taw = 0.0, tawb = 0.0, tai = 0.0, tac = 0.0;
            for (int s = 0; s < SEGS; ++s) {
                float4 p = g_part[t * SEGS + s];
                taw += p.x; tawb += p.y; tai += p.z; tac += p.w;
            }
            double wbce = tawb / taw;
            double uni  = tac - tai;
            double wiou = 1.0 - (tai + 1.0) / (uni + 1.0);
            sh2[t] = wbce + wiou;
        }
        __syncthreads();
        if (t == 0) {
            double z = 0.0;
#pragma unroll
            for (int i = 0; i < B; ++i) z += sh2[i];
            out[0] = (float)(z / (double)B);
            g_done = 0;   // reset for next (graph-replayed) execution
        }
    }
}

// ---------------------------------------------------------------------------
// Entry: in-kernel mask dtype probe (uniform across block). int64 LE high
// words are all zero; int32 random {0,1} data has a nonzero odd int within
// the first 1024 ints with probability 1 - 2^-512.
// ---------------------------------------------------------------------------
__global__ void __launch_bounds__(NT)
fused_kernel(const float* __restrict__ pred, const int* __restrict__ mask,
             float* __restrict__ out)
{
    const unsigned o = ((const unsigned*)mask)[2 * threadIdx.x + 1];
    if (__syncthreads_or(o != 0u)) fused_body<false>(pred, mask, out);
    else                           fused_body<true >(pred, mask, out);
}

// ---------------------------------------------------------------------------
extern "C" void kernel_launch(void* const* d_in, const int* in_sizes, int n_in,
                              void* d_out, int out_size)
{
    // Identify inputs by element count (robust to metadata ordering):
    // pred = 16*2*512*512 = 8388608, mask = 16*512*512 = 4194304.
    int pi = 0, mi = 1;
    if (n_in >= 2 && in_sizes[0] == 4194304 && in_sizes[1] == 8388608) {
        pi = 1; mi = 0;
    }
    const float* pred = (const float*)d_in[pi];  // [16,2,512,512] fp32
    const int*   mask = (const int*)d_in[mi];    // [16,512,512] int32 OR int64
    float* out = (float*)d_out;

    fused_kernel<<<GRID, NT>>>(pred, mask, out);
}

// round 17
// speedup vs baseline: 1.3659x; 1.0146x over previous
#include <cuda_runtime.h>
#include <cstdint>

// Problem constants
#define B    16
#define H    512
#define W    512
#define KR   15                   // pad / half-window
#define INV_WIN2 (1.0f / 961.0f)

#define SEGS 16                   // row segments per image
#define ROWS 32                   // rows per block
#define RPB  4                    // rows per batch
#define NB   (ROWS / RPB)         // 8 batches
#define RD   64                   // ring depth; rows y0-15..y0+47 = 63 distinct
#define RW   18                   // 16 data words + 2 zero pads
#define WPR  16                   // bit words per row
#define NT   512                  // threads per block (1 column each)
#define GRID (B * SEGS)           // 256

__device__ float4 g_part[GRID];   // per-block partial sums
__device__ int    g_done;         // zero-init; self-resets each run

// ---------------------------------------------------------------------------
// Build one 32-column bitmask word in one thread. bit = (v==1); {0,255}->0.
// gw = global word index (bi*8192 + row*16 + wi).
// ---------------------------------------------------------------------------
template <bool IS64>
__device__ __forceinline__ uint32_t pack_word(const int* __restrict__ m,
                                              size_t gw)
{
    uint32_t word = 0;
    if (IS64) {
        const int4* p = (const int4*)m + gw * 16;
#pragma unroll
        for (int j = 0; j < 16; ++j) {            // 16 independent LDG.128
            int4 q = p[j];                        // two int64: lows at .x/.z
            word |= (((uint32_t)(q.x == 1)) |
                     ((uint32_t)(q.z == 1) << 1)) << (2 * j);
        }
    } else {
        const int4* p = (const int4*)m + gw * 8;
#pragma unroll
        for (int j = 0; j < 8; ++j) {             // 8 independent LDG.128
            int4 q = p[j];
            word |= (((uint32_t)(q.x == 1))      |
                     ((uint32_t)(q.y == 1) << 1) |
                     ((uint32_t)(q.z == 1) << 2) |
                     ((uint32_t)(q.w == 1) << 3)) << (4 * j);
        }
    }
    return word;
}

// Horizontal 31-bit window popcount for column = 32w+lane from a padded ring
// row [pad, w0..w15, pad]. (Formula verified rel_err 0 in R4/R13.)
__device__ __forceinline__ int hcount(const uint32_t* __restrict__ rw,
                                      int base, int sh)
{
    uint32_t lo = rw[base], hi = rw[base + 1];
    return __popc(__funnelshift_r(lo, hi, sh) & 0x7FFFFFFFu);
}

// Per-pixel fused math.
__device__ __forceinline__ void pixel(float a0, float a1, int mi, float pooled,
                                      float& aw, float& awb, float& ai, float& ac)
{
    const float mf = (float)mi;
    const float wgt = 1.0f + 5.0f * fabsf(pooled - mf);

    // 2-class log-softmax, softplus form: d = a1-a0, e = exp(-|d|)
    const float d  = a1 - a0;
    const float e  = __expf(-fabsf(d));
    const float sp = __logf(1.0f + e);
    const float wb = sp + fmaxf(mi ? -d : d, 0.0f);   // -logp[target]
    const float rc = __frcp_rn(1.0f + e);
    const float sp1 = (d >= 0.0f) ? rc : e * rc;      // sigmoid(d) = p1

    aw  += wgt;
    awb += wgt * wb;
    ai  += sp1 * mf * wgt;
    ac  += (sp1 + mf) * wgt;
}

// ---------------------------------------------------------------------------
// Fused kernel, R4 skeleton: warm-up, then 8x [fill 4 rows, sync, compute 4
// rows]. Fill = per-thread word pack (no ballots). Each row's horizontal
// popcount computed ONCE by its column thread and cached in hsumS[slot][t]
// (thread-private lane -> no extra syncs); slide reads 2 cached bytes.
// ---------------------------------------------------------------------------
template <bool IS64>
__device__ __forceinline__ void fused_body(const float* __restrict__ pred,
                                           const int* __restrict__ mask,
                                           float* __restrict__ out)
{
    const int bi   = blockIdx.x >> 4;          // /SEGS
    const int seg  = blockIdx.x & (SEGS - 1);
    const int y0   = seg * ROWS;
    const int t    = threadIdx.x;
    const int lane = t & 31;
    const int w    = t >> 5;

    const int base = w + (lane >= 15);         // hcount word select
    const int sh   = (lane + 17) & 31;         // hcount funnel shift

    __shared__ uint32_t ring[RD][RW];          // 4.6 KB padded bitmask rows
    __shared__ uint8_t  hsumS[RD][W];          // 32 KB cached 31-popcounts

    // Zero pad words (row-invariant zeros); covered by warm-up sync.
    if (t < 2 * RD) ring[t >> 1][(t & 1) ? (RW - 1) : 0] = 0u;

    // Warm-up fill: rows y0-15 .. y0+15 (31 rows x 16 words = 496 tasks).
    for (int task = t; task < 31 * WPR; task += NT) {
        const int row = y0 - 15 + (task >> 4);
        const int wi  = task & 15;
        uint32_t word = 0u;
        if (row >= 0 && row < H)
            word = pack_word<IS64>(mask,
                    (size_t)bi * (H * WPR) + (size_t)row * WPR + wi);
        ring[row & (RD - 1)][1 + wi] = word;
    }
    __syncthreads();

    // vsum init: hcount rows y0-15..y0+15 once, cache, and sum.
    int vs = 0;
#pragma unroll
    for (int k = -KR; k <= KR; ++k) {
        const int slot = (y0 + k) & (RD - 1);
        const int h = hcount(ring[slot], base, sh);
        hsumS[slot][t] = (uint8_t)h;
        vs += h;
    }

    const float* p0 = pred + (size_t)bi * 524288 + t;   // ch0, column t
    const float* p1 = p0 + 262144;                      // ch1
    float aw = 0.0f, awb = 0.0f, ai = 0.0f, ac = 0.0f;

    for (int it = 0; it < NB; ++it) {
        const int yb = y0 + it * RPB;

        // Fill 4 lookahead rows yb+16..yb+19 (64 word-tasks, threads 0..63).
        if (t < RPB * WPR) {
            const int row = yb + KR + 1 + (t >> 4);
            const int wi  = t & 15;
            uint32_t word = 0u;
            if (row < H)
                word = pack_word<IS64>(mask,
                        (size_t)bi * (H * WPR) + (size_t)row * WPR + wi);
            ring[row & (RD - 1)][1 + wi] = word;
        }
        __syncthreads();
        // Ring slots are written once per block (span 63 rows <= depth 64):
        // only fill(it) -> read(it) ordering is needed, enforced here.

        // hcount the 4 new rows once; hsumS[slot][t] is thread-private
        // (written and read only by column thread t) -> no second sync.
#pragma unroll
        for (int r = 0; r < RPB; ++r) {
            const int slot = (yb + KR + 1 + r) & (RD - 1);
            hsumS[slot][t] = (uint8_t)hcount(ring[slot], base, sh);
        }

        // Compute 4 rows; slide via cached bytes (exact integer arithmetic).
#pragma unroll
        for (int r = 0; r < RPB; ++r) {
            const int y = yb + r;

            const int mi = (ring[y & (RD - 1)][1 + w] >> lane) & 1;
            const float a0 = p0[(size_t)y * W];
            const float a1 = p1[(size_t)y * W];

            pixel(a0, a1, mi, (float)vs * INV_WIN2, aw, awb, ai, ac);

            vs += (int)hsumS[(y + KR + 1) & (RD - 1)][t]
                - (int)hsumS[(y - KR) & (RD - 1)][t];
        }
    }

    // Deterministic reduction: warp butterfly + fixed-order combine.
#pragma unroll
    for (int o = 16; o > 0; o >>= 1) {
        aw  += __shfl_xor_sync(0xFFFFFFFFu, aw,  o);
        awb += __shfl_xor_sync(0xFFFFFFFFu, awb, o);
        ai  += __shfl_xor_sync(0xFFFFFFFFu, ai,  o);
        ac  += __shfl_xor_sync(0xFFFFFFFFu, ac,  o);
    }
    __shared__ float4 s4[NT / 32];
    __shared__ int amLast;
    if (lane == 0) s4[w] = make_float4(aw, awb, ai, ac);
    __syncthreads();
    if (t == 0) {
        float4 acc = s4[0];
#pragma unroll
        for (int i = 1; i < NT / 32; ++i) {
            float4 p = s4[i];
            acc.x += p.x; acc.y += p.y; acc.z += p.z; acc.w += p.w;
        }
        g_part[blockIdx.x] = acc;
        __threadfence();
        amLast = (atomicAdd(&g_done, 1) == GRID - 1);
    }
    __syncthreads();

    // Last block finalizes (deterministic fixed-order reads of g_part).
    if (amLast) {
        __shared__ double sh2[B];
        if (t < B) {
            double taw = 0.0, tawb = 0.0, tai = 0.0, tac = 0.0;
            for (int s = 0; s < SEGS; ++s) {
                float4 p = g_part[t * SEGS + s];
                taw += p.x; tawb += p.y; tai += p.z; tac += p.w;
            }
            double wbce = tawb / taw;
            double uni  = tac - tai;
            double wiou = 1.0 - (tai + 1.0) / (uni + 1.0);
            sh2[t] = wbce + wiou;
        }
        __syncthreads();
        if (t == 0) {
            double z = 0.0;
#pragma unroll
            for (int i = 0; i < B; ++i) z += sh2[i];
            out[0] = (float)(z / (double)B);
            g_done = 0;   // reset for next (graph-replayed) execution
        }
    }
}

// ---------------------------------------------------------------------------
// Entry: in-kernel mask dtype probe (uniform across block). int64 LE high
// words are all zero; int32 random {0,1} data has a nonzero odd int within
// the first 1024 ints with probability 1 - 2^-512.
// ---------------------------------------------------------------------------
__global__ void __launch_bounds__(NT)
fused_kernel(const float* __restrict__ pred, const int* __restrict__ mask,
             float* __restrict__ out)
{
    const unsigned o = ((const unsigned*)mask)[2 * threadIdx.x + 1];
    if (__syncthreads_or(o != 0u)) fused_body<false>(pred, mask, out);
    else                           fused_body<true >(pred, mask, out);
}

// ---------------------------------------------------------------------------
extern "C" void kernel_launch(void* const* d_in, const int* in_sizes, int n_in,
                              void* d_out, int out_size)
{
    // Identify inputs by element count (robust to metadata ordering):
    // pred = 16*2*512*512 = 8388608, mask = 16*512*512 = 4194304.
    int pi = 0, mi = 1;
    if (n_in >= 2 && in_sizes[0] == 4194304 && in_sizes[1] == 8388608) {
        pi = 1; mi = 0;
    }
    const float* pred = (const float*)d_in[pi];  // [16,2,512,512] fp32
    const int*   mask = (const int*)d_in[mi];    // [16,512,512] int32 OR int64
    float* out = (float*)d_out;

    fused_kernel<<<GRID, NT>>>(pred, mask, out);
}